// round 9
// baseline (speedup 1.0000x reference)
#include <cuda_runtime.h>
#include <cuda_bf16.h>
#include <cstdint>
#include <cstring>

#define Dd 128
#define NN 50000
#define NE 625000
#define RS 132                       // smem A row stride in bf16 elems (pad vs conflicts)
#define SMEM_BYTES (128 * RS * 2 * 2 + 2048)   // hi+lo planes + LN reduction
#define NT 512                       // threads per block (16 warps)

// ---------------------------------------------------------------------------
// scratch (static device memory; no runtime allocation)
// ---------------------------------------------------------------------------
__device__ float g_P[(size_t)NN * Dd];
__device__ float g_Q[(size_t)NN * Dd];
// Pre-baked B fragments in mma.m16n8k16 lane layout.
// [matrix 0..3 = W1a,W1b,W1c,W2][hi/lo][kstep 0..7][npair 0..7][lane 0..31]
__device__ uint4 g_Wfrag[4][2][8][8][32];
__device__ int g_idx64;

// ---------------------------------------------------------------------------
// helpers
// ---------------------------------------------------------------------------
__device__ __forceinline__ uint32_t pk(float x, float y) {
    __nv_bfloat162 h = __float22bfloat162_rn(make_float2(x, y));
    uint32_t u;
    memcpy(&u, &h, 4);
    return u;   // low 16 bits = x
}

__device__ __forceinline__ void mma16816(float d[4], const uint32_t a[4],
                                         uint32_t b0, uint32_t b1) {
    asm volatile(
        "mma.sync.aligned.m16n8k16.row.col.f32.bf16.bf16.f32 "
        "{%0,%1,%2,%3}, {%4,%5,%6,%7}, {%8,%9}, {%0,%1,%2,%3};"
        : "+f"(d[0]), "+f"(d[1]), "+f"(d[2]), "+f"(d[3])
        : "r"(a[0]), "r"(a[1]), "r"(a[2]), "r"(a[3]), "r"(b0), "r"(b1));
}

// split-bf16 GEMM, warp tile 16 rows x 64 cols:
// acc += A_tile @ W[mat]; products Ahi*Whi + Ahi*Wlo (shared A load) + Alo*Whi
__device__ __forceinline__ void gemm3(float (&acc)[8][4],
                                      const __nv_bfloat16* __restrict__ Ahi,
                                      const __nv_bfloat16* __restrict__ Alo,
                                      int mat, int m0, int nw, int g, int t, int lane) {
    // pass 0: A = hi plane, both W images
    #pragma unroll
    for (int ks = 0; ks < 8; ++ks) {
        uint32_t a[4];
        {
            const __nv_bfloat16* r0 = Ahi + (size_t)(m0 + g) * RS + ks * 16 + 2 * t;
            const __nv_bfloat16* r1 = r0 + 8 * RS;
            a[0] = *(const uint32_t*)r0;
            a[1] = *(const uint32_t*)r1;
            a[2] = *(const uint32_t*)(r0 + 8);
            a[3] = *(const uint32_t*)(r1 + 8);
        }
        #pragma unroll
        for (int p = 0; p < 2; ++p) {
            const uint4 (*B)[8][32] = g_Wfrag[mat][p];
            #pragma unroll
            for (int np = 0; np < 4; ++np) {
                uint4 bv = B[ks][nw * 4 + np][lane];
                mma16816(acc[2 * np],     a, bv.x, bv.y);
                mma16816(acc[2 * np + 1], a, bv.z, bv.w);
            }
        }
    }
    // pass 1: A = lo plane, W hi image
    #pragma unroll
    for (int ks = 0; ks < 8; ++ks) {
        uint32_t a[4];
        {
            const __nv_bfloat16* r0 = Alo + (size_t)(m0 + g) * RS + ks * 16 + 2 * t;
            const __nv_bfloat16* r1 = r0 + 8 * RS;
            a[0] = *(const uint32_t*)r0;
            a[1] = *(const uint32_t*)r1;
            a[2] = *(const uint32_t*)(r0 + 8);
            a[3] = *(const uint32_t*)(r1 + 8);
        }
        const uint4 (*B)[8][32] = g_Wfrag[mat][0];
        #pragma unroll
        for (int np = 0; np < 4; ++np) {
            uint4 bv = B[ks][nw * 4 + np][lane];
            mma16816(acc[2 * np],     a, bv.x, bv.y);
            mma16816(acc[2 * np + 1], a, bv.z, bv.w);
        }
    }
}

// load [128 x 128] fp32 tile, split into bf16 hi/lo planes in smem
__device__ __forceinline__ void cvt_tile(__nv_bfloat16* __restrict__ Ahi,
                                         __nv_bfloat16* __restrict__ Alo,
                                         const float* __restrict__ src,
                                         int r0, int rmax, int tid) {
    for (int i = tid; i < 128 * 32; i += NT) {
        int rr = i >> 5, c4 = i & 31;
        int gr = r0 + rr;
        float4 v = make_float4(0.f, 0.f, 0.f, 0.f);
        if (gr < rmax) v = *(const float4*)(src + (size_t)gr * Dd + c4 * 4);
        __nv_bfloat162 h01 = __float22bfloat162_rn(make_float2(v.x, v.y));
        float2 f01 = __bfloat1622float2(h01);
        __nv_bfloat162 h23 = __float22bfloat162_rn(make_float2(v.z, v.w));
        float2 f23 = __bfloat1622float2(h23);
        uint32_t* dh = (uint32_t*)(Ahi + (size_t)rr * RS) + c4 * 2;
        uint32_t* dl = (uint32_t*)(Alo + (size_t)rr * RS) + c4 * 2;
        dh[0] = pk(v.x, v.y);
        dh[1] = pk(v.z, v.w);
        dl[0] = pk(v.x - f01.x, v.y - f01.y);
        dl[1] = pk(v.z - f23.x, v.w - f23.y);
    }
}

// ---------------------------------------------------------------------------
// setup kernels
// ---------------------------------------------------------------------------
__global__ void detect_idx_kernel(const void* __restrict__ idx) {
    if (threadIdx.x == 0 && blockIdx.x == 0) {
        const long long* p = (const long long*)idx;
        int ok = 1;
        for (int i = 0; i < 1024; ++i) {
            long long v = p[i];
            if (v < 0 || v >= (long long)NN) { ok = 0; break; }
        }
        g_idx64 = ok;
    }
}

__global__ void weights_kernel(const float* __restrict__ W1, const float* __restrict__ W2) {
    int m = blockIdx.x;   // 0:W1a 1:W1b 2:W1c 3:W2
    const float* src = (m < 3) ? (W1 + (size_t)m * Dd * Dd) : W2;
    for (int idx = threadIdx.x; idx < 2 * 8 * 8 * 32; idx += blockDim.x) {
        int p = idx >> 11;          // 0 hi, 1 lo
        int rem = idx & 2047;
        int ks = rem >> 8;
        int np = (rem >> 5) & 7;
        int lane = rem & 31;
        int g = lane >> 2, t = lane & 3;
        uint32_t vals[4];
        #pragma unroll
        for (int half = 0; half < 2; ++half) {
            int n = (np * 2 + half) * 8 + g;
            float w[4];
            w[0] = src[(size_t)(ks * 16 + 2 * t) * Dd + n];
            w[1] = src[(size_t)(ks * 16 + 2 * t + 1) * Dd + n];
            w[2] = src[(size_t)(ks * 16 + 2 * t + 8) * Dd + n];
            w[3] = src[(size_t)(ks * 16 + 2 * t + 9) * Dd + n];
            float s[4];
            #pragma unroll
            for (int j = 0; j < 4; ++j) {
                float hv = __bfloat162float(__float2bfloat16(w[j]));
                s[j] = p ? (w[j] - hv) : w[j];
            }
            vals[half * 2 + 0] = pk(s[0], s[1]);
            vals[half * 2 + 1] = pk(s[2], s[3]);
        }
        g_Wfrag[m][p][ks][np][lane] = make_uint4(vals[0], vals[1], vals[2], vals[3]);
    }
}

// ---------------------------------------------------------------------------
// node projection: P = X @ W1a, Q = X @ W1b (128-node tiles, 16 warps)
// ---------------------------------------------------------------------------
__global__ __launch_bounds__(NT, 2) void node_kernel(const float* __restrict__ node_attr) {
    extern __shared__ char smem[];
    __nv_bfloat16* Ahi = (__nv_bfloat16*)smem;
    __nv_bfloat16* Alo = Ahi + 128 * RS;

    const int tid = threadIdx.x;
    const int lane = tid & 31, w = tid >> 5;
    const int g = lane >> 2, t = lane & 3;
    const int m0 = (w & 7) * 16, nw = w >> 3, nc0 = nw * 64;
    const int r0 = blockIdx.x * 128;

    cvt_tile(Ahi, Alo, node_attr, r0, NN, tid);
    __syncthreads();

    float acc[8][4];
    #pragma unroll 1
    for (int mat = 0; mat < 2; ++mat) {
        #pragma unroll
        for (int nt = 0; nt < 8; ++nt)
            #pragma unroll
            for (int j = 0; j < 4; ++j) acc[nt][j] = 0.f;

        gemm3(acc, Ahi, Alo, mat, m0, nw, g, t, lane);

        float* dst = mat ? g_Q : g_P;
        #pragma unroll
        for (int h = 0; h < 2; ++h) {
            int gr = r0 + m0 + h * 8 + g;
            if (gr < NN) {
                #pragma unroll
                for (int nt = 0; nt < 8; ++nt) {
                    int c = nc0 + nt * 8 + 2 * t;
                    *(float2*)(dst + (size_t)gr * Dd + c) =
                        make_float2(acc[nt][h * 2], acc[nt][h * 2 + 1]);
                }
            }
        }
    }
}

// ---------------------------------------------------------------------------
// fused edge kernel (16 warps, warp tile 16x64)
// ---------------------------------------------------------------------------
__global__ __launch_bounds__(NT, 2) void edge_kernel(
    const float* __restrict__ edge_attr,
    const void* __restrict__ idx,
    const float* __restrict__ b1,
    const float* __restrict__ b2,
    const float* __restrict__ gamma,
    const float* __restrict__ beta,
    float* __restrict__ out) {
    extern __shared__ char smem[];
    __nv_bfloat16* Ahi = (__nv_bfloat16*)smem;
    __nv_bfloat16* Alo = Ahi + 128 * RS;
    float* redS  = (float*)(smem + (size_t)128 * RS * 4);   // [128][2]
    float* redS2 = redS + 256;

    const int tid = threadIdx.x;
    const int lane = tid & 31, w = tid >> 5;
    const int g = lane >> 2, t = lane & 3;
    const int m0 = (w & 7) * 16, nw = w >> 3, nc0 = nw * 64;
    const int e0 = blockIdx.x * 128;
    const int is64 = g_idx64;

    cvt_tile(Ahi, Alo, edge_attr, e0, NE, tid);
    __syncthreads();

    float acc[8][4];
    #pragma unroll
    for (int nt = 0; nt < 8; ++nt)
        #pragma unroll
        for (int j = 0; j < 4; ++j) acc[nt][j] = 0.f;

    // GEMM1: edge_attr @ W1c
    gemm3(acc, Ahi, Alo, 2, m0, nw, g, t, lane);

    // + P[sender] + Q[receiver] + b1, then ReLU
    #pragma unroll
    for (int h = 0; h < 2; ++h) {
        int e = e0 + m0 + h * 8 + g;
        if (e < NE) {
            int s, rv;
            if (is64) {
                const long long* pI = (const long long*)idx;
                s = (int)pI[e]; rv = (int)pI[NE + e];
            } else {
                const int* pI = (const int*)idx;
                s = pI[e]; rv = pI[NE + e];
            }
            const float* Pp = g_P + (size_t)s * Dd;
            const float* Qp = g_Q + (size_t)rv * Dd;
            #pragma unroll
            for (int nt = 0; nt < 8; ++nt) {
                int c = nc0 + nt * 8 + 2 * t;
                float2 pv = *(const float2*)(Pp + c);
                float2 qv = *(const float2*)(Qp + c);
                float2 bv = *(const float2*)(b1 + c);
                acc[nt][h * 2 + 0] += pv.x + qv.x + bv.x;
                acc[nt][h * 2 + 1] += pv.y + qv.y + bv.y;
            }
        }
    }
    #pragma unroll
    for (int nt = 0; nt < 8; ++nt)
        #pragma unroll
        for (int j = 0; j < 4; ++j) acc[nt][j] = fmaxf(acc[nt][j], 0.f);

    __syncthreads();   // all warps done reading edge A planes

    // store H = relu(...) as hi/lo bf16 back into the A planes
    #pragma unroll
    for (int h = 0; h < 2; ++h) {
        int row = m0 + h * 8 + g;
        #pragma unroll
        for (int nt = 0; nt < 8; ++nt) {
            int c = nc0 + nt * 8 + 2 * t;
            float x0 = acc[nt][h * 2], x1 = acc[nt][h * 2 + 1];
            __nv_bfloat162 hh = __float22bfloat162_rn(make_float2(x0, x1));
            float2 hf = __bfloat1622float2(hh);
            *(uint32_t*)(Ahi + (size_t)row * RS + c) = pk(x0, x1);
            *(uint32_t*)(Alo + (size_t)row * RS + c) = pk(x0 - hf.x, x1 - hf.y);
        }
    }
    __syncthreads();

    #pragma unroll
    for (int nt = 0; nt < 8; ++nt)
        #pragma unroll
        for (int j = 0; j < 4; ++j) acc[nt][j] = 0.f;

    // GEMM2: H @ W2
    gemm3(acc, Ahi, Alo, 3, m0, nw, g, t, lane);

    // LayerNorm: add b2, row partial sums, cross-n-warp reduction via smem
    #pragma unroll
    for (int h = 0; h < 2; ++h) {
        int row = m0 + h * 8 + g;
        float s = 0.f, s2 = 0.f;
        #pragma unroll
        for (int nt = 0; nt < 8; ++nt) {
            int c = nc0 + nt * 8 + 2 * t;
            float2 bv = *(const float2*)(b2 + c);
            float v0 = acc[nt][h * 2] + bv.x;
            float v1 = acc[nt][h * 2 + 1] + bv.y;
            acc[nt][h * 2] = v0;
            acc[nt][h * 2 + 1] = v1;
            s += v0 + v1;
            s2 += v0 * v0 + v1 * v1;
        }
        s  += __shfl_xor_sync(0xFFFFFFFFu, s, 1);
        s  += __shfl_xor_sync(0xFFFFFFFFu, s, 2);
        s2 += __shfl_xor_sync(0xFFFFFFFFu, s2, 1);
        s2 += __shfl_xor_sync(0xFFFFFFFFu, s2, 2);
        if (t == 0) {
            redS[row * 2 + nw] = s;
            redS2[row * 2 + nw] = s2;
        }
    }
    __syncthreads();

    #pragma unroll
    for (int h = 0; h < 2; ++h) {
        int row = m0 + h * 8 + g;
        int e = e0 + row;
        if (e < NE) {
            float S  = redS[row * 2] + redS[row * 2 + 1];
            float S2 = redS2[row * 2] + redS2[row * 2 + 1];
            float mu = S * (1.f / 128.f);
            float var = S2 * (1.f / 128.f) - mu * mu;
            float inv = rsqrtf(var + 1e-5f);
            #pragma unroll
            for (int nt = 0; nt < 8; ++nt) {
                int c = nc0 + nt * 8 + 2 * t;
                float2 gv = *(const float2*)(gamma + c);
                float2 bv = *(const float2*)(beta + c);
                float2 o;
                o.x = (acc[nt][h * 2] - mu) * inv * gv.x + bv.x;
                o.y = (acc[nt][h * 2 + 1] - mu) * inv * gv.y + bv.y;
                *(float2*)(out + (size_t)e * Dd + c) = o;
            }
        }
    }
}

// ---------------------------------------------------------------------------
extern "C" void kernel_launch(void* const* d_in, const int* in_sizes, int n_in,
                              void* d_out, int out_size) {
    const float* node_attr = (const float*)d_in[0];
    const void*  eidx      = d_in[1];
    const float* edge_attr = (const float*)d_in[2];
    const float* W1        = (const float*)d_in[3];
    const float* b1        = (const float*)d_in[4];
    const float* W2        = (const float*)d_in[5];
    const float* b2        = (const float*)d_in[6];
    const float* gamma     = (const float*)d_in[7];
    const float* beta      = (const float*)d_in[8];
    float* out = (float*)d_out;

    cudaFuncSetAttribute(node_kernel, cudaFuncAttributeMaxDynamicSharedMemorySize, SMEM_BYTES);
    cudaFuncSetAttribute(edge_kernel, cudaFuncAttributeMaxDynamicSharedMemorySize, SMEM_BYTES);

    detect_idx_kernel<<<1, 32>>>(eidx);
    weights_kernel<<<4, 256>>>(W1, W2);

    node_kernel<<<(NN + 127) / 128, NT, SMEM_BYTES>>>(node_attr);
    edge_kernel<<<(NE + 127) / 128, NT, SMEM_BYTES>>>(edge_attr, eidx, b1, b2,
                                                      gamma, beta, out);
}

// round 12
// speedup vs baseline: 3.6159x; 3.6159x over previous
#include <cuda_runtime.h>
#include <cuda_bf16.h>
#include <cstdint>
#include <cstring>

#define Dd 128
#define NN 50000
#define NE 625000
#define RS 136                       // smem A row stride in bf16 (272B = 16B-multiple for ldmatrix)
#define SMEM_BYTES (128 * RS * 2 * 2 + 2048)   // hi+lo planes + LN reduction
#define NT 256                       // threads per block (8 warps)

// ---------------------------------------------------------------------------
// scratch (static device memory; no runtime allocation)
// ---------------------------------------------------------------------------
__device__ float g_P[(size_t)NN * Dd];
__device__ float g_Q[(size_t)NN * Dd];
// Pre-baked B fragments in mma.m16n8k16 lane layout.
// [matrix 0..3 = W1a,W1b,W1c,W2][hi/lo][kstep 0..7][npair 0..7][lane 0..31]
__device__ uint4 g_Wfrag[4][2][8][8][32];
__device__ int g_idx64;

// ---------------------------------------------------------------------------
// helpers
// ---------------------------------------------------------------------------
__device__ __forceinline__ uint32_t pk(float x, float y) {
    __nv_bfloat162 h = __float22bfloat162_rn(make_float2(x, y));
    uint32_t u;
    memcpy(&u, &h, 4);
    return u;   // low 16 bits = x
}

__device__ __forceinline__ uint32_t smem_u32(const void* p) {
    uint32_t a;
    asm("{ .reg .u64 t; cvta.to.shared.u64 t, %1; cvt.u32.u64 %0, t; }"
        : "=r"(a) : "l"(p));
    return a;
}

__device__ __forceinline__ void ldsm4(uint32_t a[4], uint32_t addr) {
    asm volatile("ldmatrix.sync.aligned.m8n8.x4.shared.b16 {%0,%1,%2,%3}, [%4];"
                 : "=r"(a[0]), "=r"(a[1]), "=r"(a[2]), "=r"(a[3]) : "r"(addr));
}

__device__ __forceinline__ void mma16816(float d[4], const uint32_t a[4],
                                         uint32_t b0, uint32_t b1) {
    asm volatile(
        "mma.sync.aligned.m16n8k16.row.col.f32.bf16.bf16.f32 "
        "{%0,%1,%2,%3}, {%4,%5,%6,%7}, {%8,%9}, {%0,%1,%2,%3};"
        : "+f"(d[0]), "+f"(d[1]), "+f"(d[2]), "+f"(d[3])
        : "r"(a[0]), "r"(a[1]), "r"(a[2]), "r"(a[3]), "r"(b0), "r"(b1));
}

// split-bf16 GEMM, warp tile 32 rows x 64 cols, single merged pass:
// per ks: load Ahi/Alo frags (ldmatrix.x4) + B hi/lo frags once;
// issue Ahi*Bhi + Ahi*Blo + Alo*Bhi (B-hi loaded ONCE, not twice).
__device__ __forceinline__ void gemm3(float (&acc)[2][8][4],
                                      uint32_t aHi, uint32_t aLo,
                                      int mat, int nw, int lane) {
    const uint4 (*Bh)[8][32] = g_Wfrag[mat][0];
    const uint4 (*Bl)[8][32] = g_Wfrag[mat][1];
    #pragma unroll
    for (int ks = 0; ks < 8; ++ks) {
        uint32_t ah[2][4], al[2][4];
        ldsm4(ah[0], aHi + ks * 32);
        ldsm4(ah[1], aHi + 16 * RS * 2 + ks * 32);
        ldsm4(al[0], aLo + ks * 32);
        ldsm4(al[1], aLo + 16 * RS * 2 + ks * 32);
        #pragma unroll
        for (int npp = 0; npp < 2; ++npp) {
            uint4 bh0 = Bh[ks][nw * 4 + 2 * npp][lane];
            uint4 bh1 = Bh[ks][nw * 4 + 2 * npp + 1][lane];
            uint4 bl0 = Bl[ks][nw * 4 + 2 * npp][lane];
            uint4 bl1 = Bl[ks][nw * 4 + 2 * npp + 1][lane];
            const int n0 = 4 * npp, n1 = n0 + 1, n2 = n0 + 2, n3 = n0 + 3;
            // Ahi x Bhi (8 independent chains)
            mma16816(acc[0][n0], ah[0], bh0.x, bh0.y);
            mma16816(acc[0][n1], ah[0], bh0.z, bh0.w);
            mma16816(acc[1][n0], ah[1], bh0.x, bh0.y);
            mma16816(acc[1][n1], ah[1], bh0.z, bh0.w);
            mma16816(acc[0][n2], ah[0], bh1.x, bh1.y);
            mma16816(acc[0][n3], ah[0], bh1.z, bh1.w);
            mma16816(acc[1][n2], ah[1], bh1.x, bh1.y);
            mma16816(acc[1][n3], ah[1], bh1.z, bh1.w);
            // Ahi x Blo
            mma16816(acc[0][n0], ah[0], bl0.x, bl0.y);
            mma16816(acc[0][n1], ah[0], bl0.z, bl0.w);
            mma16816(acc[1][n0], ah[1], bl0.x, bl0.y);
            mma16816(acc[1][n1], ah[1], bl0.z, bl0.w);
            mma16816(acc[0][n2], ah[0], bl1.x, bl1.y);
            mma16816(acc[0][n3], ah[0], bl1.z, bl1.w);
            mma16816(acc[1][n2], ah[1], bl1.x, bl1.y);
            mma16816(acc[1][n3], ah[1], bl1.z, bl1.w);
            // Alo x Bhi
            mma16816(acc[0][n0], al[0], bh0.x, bh0.y);
            mma16816(acc[0][n1], al[0], bh0.z, bh0.w);
            mma16816(acc[1][n0], al[1], bh0.x, bh0.y);
            mma16816(acc[1][n1], al[1], bh0.z, bh0.w);
            mma16816(acc[0][n2], al[0], bh1.x, bh1.y);
            mma16816(acc[0][n3], al[0], bh1.z, bh1.w);
            mma16816(acc[1][n2], al[1], bh1.x, bh1.y);
            mma16816(acc[1][n3], al[1], bh1.z, bh1.w);
        }
    }
}

// load [128 x 128] fp32 tile, split into bf16 hi/lo planes in smem
__device__ __forceinline__ void cvt_tile(__nv_bfloat16* __restrict__ Ahi,
                                         __nv_bfloat16* __restrict__ Alo,
                                         const float* __restrict__ src,
                                         int r0, int rmax, int tid) {
    for (int i = tid; i < 128 * 32; i += NT) {
        int rr = i >> 5, c4 = i & 31;
        int gr = r0 + rr;
        float4 v = make_float4(0.f, 0.f, 0.f, 0.f);
        if (gr < rmax) v = *(const float4*)(src + (size_t)gr * Dd + c4 * 4);
        __nv_bfloat162 h01 = __float22bfloat162_rn(make_float2(v.x, v.y));
        float2 f01 = __bfloat1622float2(h01);
        __nv_bfloat162 h23 = __float22bfloat162_rn(make_float2(v.z, v.w));
        float2 f23 = __bfloat1622float2(h23);
        uint32_t* dh = (uint32_t*)(Ahi + (size_t)rr * RS) + c4 * 2;
        uint32_t* dl = (uint32_t*)(Alo + (size_t)rr * RS) + c4 * 2;
        dh[0] = pk(v.x, v.y);
        dh[1] = pk(v.z, v.w);
        dl[0] = pk(v.x - f01.x, v.y - f01.y);
        dl[1] = pk(v.z - f23.x, v.w - f23.y);
    }
}

// ---------------------------------------------------------------------------
// setup kernels
// ---------------------------------------------------------------------------
__global__ void detect_idx_kernel(const void* __restrict__ idx) {
    if (threadIdx.x == 0 && blockIdx.x == 0) {
        const long long* p = (const long long*)idx;
        int ok = 1;
        for (int i = 0; i < 1024; ++i) {
            long long v = p[i];
            if (v < 0 || v >= (long long)NN) { ok = 0; break; }
        }
        g_idx64 = ok;
    }
}

__global__ void weights_kernel(const float* __restrict__ W1, const float* __restrict__ W2) {
    int m = blockIdx.x;   // 0:W1a 1:W1b 2:W1c 3:W2
    const float* src = (m < 3) ? (W1 + (size_t)m * Dd * Dd) : W2;
    for (int idx = threadIdx.x; idx < 2 * 8 * 8 * 32; idx += blockDim.x) {
        int p = idx >> 11;          // 0 hi, 1 lo
        int rem = idx & 2047;
        int ks = rem >> 8;
        int np = (rem >> 5) & 7;
        int lane = rem & 31;
        int g = lane >> 2, t = lane & 3;
        uint32_t vals[4];
        #pragma unroll
        for (int half = 0; half < 2; ++half) {
            int n = (np * 2 + half) * 8 + g;
            float w[4];
            w[0] = src[(size_t)(ks * 16 + 2 * t) * Dd + n];
            w[1] = src[(size_t)(ks * 16 + 2 * t + 1) * Dd + n];
            w[2] = src[(size_t)(ks * 16 + 2 * t + 8) * Dd + n];
            w[3] = src[(size_t)(ks * 16 + 2 * t + 9) * Dd + n];
            float s[4];
            #pragma unroll
            for (int j = 0; j < 4; ++j) {
                float hv = __bfloat162float(__float2bfloat16(w[j]));
                s[j] = p ? (w[j] - hv) : w[j];
            }
            vals[half * 2 + 0] = pk(s[0], s[1]);
            vals[half * 2 + 1] = pk(s[2], s[3]);
        }
        g_Wfrag[m][p][ks][np][lane] = make_uint4(vals[0], vals[1], vals[2], vals[3]);
    }
}

// ---------------------------------------------------------------------------
// node projection: P = X @ W1a, Q = X @ W1b (128-node tiles)
// ---------------------------------------------------------------------------
__global__ __launch_bounds__(NT, 2) void node_kernel(const float* __restrict__ node_attr) {
    extern __shared__ char smem[];
    __nv_bfloat16* Ahi = (__nv_bfloat16*)smem;
    __nv_bfloat16* Alo = Ahi + 128 * RS;

    const int tid = threadIdx.x;
    const int lane = tid & 31, w = tid >> 5;
    const int g = lane >> 2, t = lane & 3;
    const int m0 = (w & 3) * 32, nw = w >> 2, nc0 = nw * 64;
    const int r0 = blockIdx.x * 128;

    cvt_tile(Ahi, Alo, node_attr, r0, NN, tid);
    __syncthreads();

    // lane-resolved ldmatrix base addresses (m-tile 0 of this warp)
    const int lrow = m0 + (lane & 15);
    const uint32_t aOff = (uint32_t)lrow * RS * 2 + (uint32_t)(lane >> 4) * 16;
    const uint32_t aHiA = smem_u32(Ahi) + aOff;
    const uint32_t aLoA = smem_u32(Alo) + aOff;

    float acc[2][8][4];
    #pragma unroll 1
    for (int mat = 0; mat < 2; ++mat) {
        #pragma unroll
        for (int mt = 0; mt < 2; ++mt)
            #pragma unroll
            for (int nt = 0; nt < 8; ++nt)
                #pragma unroll
                for (int j = 0; j < 4; ++j) acc[mt][nt][j] = 0.f;

        gemm3(acc, aHiA, aLoA, mat, nw, lane);

        float* dst = mat ? g_Q : g_P;
        #pragma unroll
        for (int mt = 0; mt < 2; ++mt) {
            #pragma unroll
            for (int h = 0; h < 2; ++h) {
                int gr = r0 + m0 + mt * 16 + h * 8 + g;
                if (gr < NN) {
                    #pragma unroll
                    for (int nt = 0; nt < 8; ++nt) {
                        int c = nc0 + nt * 8 + 2 * t;
                        *(float2*)(dst + (size_t)gr * Dd + c) =
                            make_float2(acc[mt][nt][h * 2], acc[mt][nt][h * 2 + 1]);
                    }
                }
            }
        }
    }
}

// ---------------------------------------------------------------------------
// fused edge kernel
// ---------------------------------------------------------------------------
__global__ __launch_bounds__(NT, 2) void edge_kernel(
    const float* __restrict__ edge_attr,
    const void* __restrict__ idx,
    const float* __restrict__ b1,
    const float* __restrict__ b2,
    const float* __restrict__ gamma,
    const float* __restrict__ beta,
    float* __restrict__ out) {
    extern __shared__ char smem[];
    __nv_bfloat16* Ahi = (__nv_bfloat16*)smem;
    __nv_bfloat16* Alo = Ahi + 128 * RS;
    float* redS  = (float*)(smem + (size_t)128 * RS * 4);   // [128][2]
    float* redS2 = redS + 256;

    const int tid = threadIdx.x;
    const int lane = tid & 31, w = tid >> 5;
    const int g = lane >> 2, t = lane & 3;
    const int m0 = (w & 3) * 32, nw = w >> 2, nc0 = nw * 64;
    const int e0 = blockIdx.x * 128;
    const int is64 = g_idx64;

    cvt_tile(Ahi, Alo, edge_attr, e0, NE, tid);
    __syncthreads();

    const int lrow = m0 + (lane & 15);
    const uint32_t aOff = (uint32_t)lrow * RS * 2 + (uint32_t)(lane >> 4) * 16;
    const uint32_t aHiA = smem_u32(Ahi) + aOff;
    const uint32_t aLoA = smem_u32(Alo) + aOff;

    float acc[2][8][4];
    #pragma unroll
    for (int mt = 0; mt < 2; ++mt)
        #pragma unroll
        for (int nt = 0; nt < 8; ++nt)
            #pragma unroll
            for (int j = 0; j < 4; ++j) acc[mt][nt][j] = 0.f;

    // GEMM1: edge_attr @ W1c
    gemm3(acc, aHiA, aLoA, 2, nw, lane);

    // + P[sender] + Q[receiver] + b1, then ReLU
    #pragma unroll
    for (int mt = 0; mt < 2; ++mt) {
        #pragma unroll
        for (int h = 0; h < 2; ++h) {
            int e = e0 + m0 + mt * 16 + h * 8 + g;
            if (e < NE) {
                int s, rv;
                if (is64) {
                    const long long* pI = (const long long*)idx;
                    s = (int)pI[e]; rv = (int)pI[NE + e];
                } else {
                    const int* pI = (const int*)idx;
                    s = pI[e]; rv = pI[NE + e];
                }
                const float* Pp = g_P + (size_t)s * Dd;
                const float* Qp = g_Q + (size_t)rv * Dd;
                #pragma unroll
                for (int nt = 0; nt < 8; ++nt) {
                    int c = nc0 + nt * 8 + 2 * t;
                    float2 pv = *(const float2*)(Pp + c);
                    float2 qv = *(const float2*)(Qp + c);
                    float2 bv = *(const float2*)(b1 + c);
                    acc[mt][nt][h * 2 + 0] += pv.x + qv.x + bv.x;
                    acc[mt][nt][h * 2 + 1] += pv.y + qv.y + bv.y;
                }
            }
        }
    }
    #pragma unroll
    for (int mt = 0; mt < 2; ++mt)
        #pragma unroll
        for (int nt = 0; nt < 8; ++nt)
            #pragma unroll
            for (int j = 0; j < 4; ++j) acc[mt][nt][j] = fmaxf(acc[mt][nt][j], 0.f);

    __syncthreads();   // all warps done reading edge A planes

    // store H = relu(...) as hi/lo bf16 back into the A planes
    #pragma unroll
    for (int mt = 0; mt < 2; ++mt) {
        #pragma unroll
        for (int h = 0; h < 2; ++h) {
            int row = m0 + mt * 16 + h * 8 + g;
            #pragma unroll
            for (int nt = 0; nt < 8; ++nt) {
                int c = nc0 + nt * 8 + 2 * t;
                float x0 = acc[mt][nt][h * 2], x1 = acc[mt][nt][h * 2 + 1];
                __nv_bfloat162 hh = __float22bfloat162_rn(make_float2(x0, x1));
                float2 hf = __bfloat1622float2(hh);
                *(uint32_t*)(Ahi + (size_t)row * RS + c) = pk(x0, x1);
                *(uint32_t*)(Alo + (size_t)row * RS + c) = pk(x0 - hf.x, x1 - hf.y);
            }
        }
    }
    __syncthreads();

    #pragma unroll
    for (int mt = 0; mt < 2; ++mt)
        #pragma unroll
        for (int nt = 0; nt < 8; ++nt)
            #pragma unroll
            for (int j = 0; j < 4; ++j) acc[mt][nt][j] = 0.f;

    // GEMM2: H @ W2
    gemm3(acc, aHiA, aLoA, 3, nw, lane);

    // LayerNorm: add b2, row partial sums, cross-n-warp reduction via smem
    #pragma unroll
    for (int mt = 0; mt < 2; ++mt) {
        #pragma unroll
        for (int h = 0; h < 2; ++h) {
            int row = m0 + mt * 16 + h * 8 + g;
            float s = 0.f, s2 = 0.f;
            #pragma unroll
            for (int nt = 0; nt < 8; ++nt) {
                int c = nc0 + nt * 8 + 2 * t;
                float2 bv = *(const float2*)(b2 + c);
                float v0 = acc[mt][nt][h * 2] + bv.x;
                float v1 = acc[mt][nt][h * 2 + 1] + bv.y;
                acc[mt][nt][h * 2] = v0;
                acc[mt][nt][h * 2 + 1] = v1;
                s += v0 + v1;
                s2 += v0 * v0 + v1 * v1;
            }
            s  += __shfl_xor_sync(0xFFFFFFFFu, s, 1);
            s  += __shfl_xor_sync(0xFFFFFFFFu, s, 2);
            s2 += __shfl_xor_sync(0xFFFFFFFFu, s2, 1);
            s2 += __shfl_xor_sync(0xFFFFFFFFu, s2, 2);
            if (t == 0) {
                redS[row * 2 + nw] = s;
                redS2[row * 2 + nw] = s2;
            }
        }
    }
    __syncthreads();

    #pragma unroll
    for (int mt = 0; mt < 2; ++mt) {
        #pragma unroll
        for (int h = 0; h < 2; ++h) {
            int row = m0 + mt * 16 + h * 8 + g;
            int e = e0 + row;
            if (e < NE) {
                float S  = redS[row * 2] + redS[row * 2 + 1];
                float S2 = redS2[row * 2] + redS2[row * 2 + 1];
                float mu = S * (1.f / 128.f);
                float var = S2 * (1.f / 128.f) - mu * mu;
                float inv = rsqrtf(var + 1e-5f);
                #pragma unroll
                for (int nt = 0; nt < 8; ++nt) {
                    int c = nc0 + nt * 8 + 2 * t;
                    float2 gv = *(const float2*)(gamma + c);
                    float2 bv = *(const float2*)(beta + c);
                    float2 o;
                    o.x = (acc[mt][nt][h * 2] - mu) * inv * gv.x + bv.x;
                    o.y = (acc[mt][nt][h * 2 + 1] - mu) * inv * gv.y + bv.y;
                    *(float2*)(out + (size_t)e * Dd + c) = o;
                }
            }
        }
    }
}

// ---------------------------------------------------------------------------
extern "C" void kernel_launch(void* const* d_in, const int* in_sizes, int n_in,
                              void* d_out, int out_size) {
    const float* node_attr = (const float*)d_in[0];
    const void*  eidx      = d_in[1];
    const float* edge_attr = (const float*)d_in[2];
    const float* W1        = (const float*)d_in[3];
    const float* b1        = (const float*)d_in[4];
    const float* W2        = (const float*)d_in[5];
    const float* b2        = (const float*)d_in[6];
    const float* gamma     = (const float*)d_in[7];
    const float* beta      = (const float*)d_in[8];
    float* out = (float*)d_out;

    cudaFuncSetAttribute(node_kernel, cudaFuncAttributeMaxDynamicSharedMemorySize, SMEM_BYTES);
    cudaFuncSetAttribute(edge_kernel, cudaFuncAttributeMaxDynamicSharedMemorySize, SMEM_BYTES);

    detect_idx_kernel<<<1, 32>>>(eidx);
    weights_kernel<<<4, 256>>>(W1, W2);

    node_kernel<<<(NN + 127) / 128, NT, SMEM_BYTES>>>(node_attr);
    edge_kernel<<<(NE + 127) / 128, NT, SMEM_BYTES>>>(edge_attr, eidx, b1, b2,
                                                      gamma, beta, out);
}

// round 14
// speedup vs baseline: 3.9557x; 1.0940x over previous
#include <cuda_runtime.h>
#include <cuda_bf16.h>
#include <cuda_fp16.h>
#include <cstdint>
#include <cstring>

#define Dd 128
#define NN 50000
#define NE 625000
#define RS 136                       // smem A row stride in fp16 elems (272B, 16B-multiple)
#define SMEM_BYTES (128 * RS * 2 * 2 + 2048)   // hi+lo planes + LN reduction
#define NT 256                       // threads per block (8 warps)

// ---------------------------------------------------------------------------
// scratch (static device memory; no runtime allocation)
// ---------------------------------------------------------------------------
__device__ float g_P[(size_t)NN * Dd];
__device__ float g_Q[(size_t)NN * Dd];
// Pre-baked B fragments (fp16 hi only) in mma.m16n8k16 lane layout.
// [matrix 0..3 = W1a,W1b,W1c,W2][kstep 0..7][npair 0..7][lane 0..31]
__device__ uint4 g_Wfrag[4][8][8][32];
__device__ int g_idx64;

// ---------------------------------------------------------------------------
// helpers
// ---------------------------------------------------------------------------
__device__ __forceinline__ uint32_t pkh(float x, float y) {
    __half2 h = __floats2half2_rn(x, y);
    uint32_t u;
    memcpy(&u, &h, 4);
    return u;   // low 16 bits = x
}

__device__ __forceinline__ uint32_t smem_u32(const void* p) {
    uint32_t a;
    asm("{ .reg .u64 t; cvta.to.shared.u64 t, %1; cvt.u32.u64 %0, t; }"
        : "=r"(a) : "l"(p));
    return a;
}

__device__ __forceinline__ void ldsm4(uint32_t a[4], uint32_t addr) {
    asm volatile("ldmatrix.sync.aligned.m8n8.x4.shared.b16 {%0,%1,%2,%3}, [%4];"
                 : "=r"(a[0]), "=r"(a[1]), "=r"(a[2]), "=r"(a[3]) : "r"(addr));
}

__device__ __forceinline__ void mma16816(float d[4], const uint32_t a[4],
                                         uint32_t b0, uint32_t b1) {
    asm volatile(
        "mma.sync.aligned.m16n8k16.row.col.f32.f16.f16.f32 "
        "{%0,%1,%2,%3}, {%4,%5,%6,%7}, {%8,%9}, {%0,%1,%2,%3};"
        : "+f"(d[0]), "+f"(d[1]), "+f"(d[2]), "+f"(d[3])
        : "r"(a[0]), "r"(a[1]), "r"(a[2]), "r"(a[3]), "r"(b0), "r"(b1));
}

// 2-product fp16 split GEMM, warp tile 32 rows x 64 cols:
// acc += (Ahi + Alo) @ Bhi[mat].  A = fp16 hi/lo planes in smem (22-bit eff.),
// B = fp16 hi fragments from global (L1-resident, 32KB/mat).
__device__ __forceinline__ void gemm2p(float (&acc)[2][8][4],
                                       uint32_t aHi, uint32_t aLo,
                                       int mat, int nw, int lane) {
    #pragma unroll
    for (int ks = 0; ks < 8; ++ks) {
        uint32_t ah[2][4], al[2][4];
        ldsm4(ah[0], aHi + ks * 32);
        ldsm4(ah[1], aHi + 16 * RS * 2 + ks * 32);
        ldsm4(al[0], aLo + ks * 32);
        ldsm4(al[1], aLo + 16 * RS * 2 + ks * 32);
        #pragma unroll
        for (int npp = 0; npp < 2; ++npp) {
            uint4 b0 = g_Wfrag[mat][ks][nw * 4 + 2 * npp][lane];
            uint4 b1 = g_Wfrag[mat][ks][nw * 4 + 2 * npp + 1][lane];
            const int n0 = 4 * npp, n1 = n0 + 1, n2 = n0 + 2, n3 = n0 + 3;
            // Ahi x Bhi (8 independent chains)
            mma16816(acc[0][n0], ah[0], b0.x, b0.y);
            mma16816(acc[0][n1], ah[0], b0.z, b0.w);
            mma16816(acc[1][n0], ah[1], b0.x, b0.y);
            mma16816(acc[1][n1], ah[1], b0.z, b0.w);
            mma16816(acc[0][n2], ah[0], b1.x, b1.y);
            mma16816(acc[0][n3], ah[0], b1.z, b1.w);
            mma16816(acc[1][n2], ah[1], b1.x, b1.y);
            mma16816(acc[1][n3], ah[1], b1.z, b1.w);
            // Alo x Bhi
            mma16816(acc[0][n0], al[0], b0.x, b0.y);
            mma16816(acc[0][n1], al[0], b0.z, b0.w);
            mma16816(acc[1][n0], al[1], b0.x, b0.y);
            mma16816(acc[1][n1], al[1], b0.z, b0.w);
            mma16816(acc[0][n2], al[0], b1.x, b1.y);
            mma16816(acc[0][n3], al[0], b1.z, b1.w);
            mma16816(acc[1][n2], al[1], b1.x, b1.y);
            mma16816(acc[1][n3], al[1], b1.z, b1.w);
        }
    }
}

// load [128 x 128] fp32 tile, split into fp16 hi/lo planes in smem
__device__ __forceinline__ void cvt_tile(__half* __restrict__ Ahi,
                                         __half* __restrict__ Alo,
                                         const float* __restrict__ src,
                                         int r0, int rmax, int tid) {
    for (int i = tid; i < 128 * 32; i += NT) {
        int rr = i >> 5, c4 = i & 31;
        int gr = r0 + rr;
        float4 v = make_float4(0.f, 0.f, 0.f, 0.f);
        if (gr < rmax) v = *(const float4*)(src + (size_t)gr * Dd + c4 * 4);
        __half2 h01 = __floats2half2_rn(v.x, v.y);
        float2 f01 = __half22float2(h01);
        __half2 h23 = __floats2half2_rn(v.z, v.w);
        float2 f23 = __half22float2(h23);
        uint32_t* dh = (uint32_t*)(Ahi + (size_t)rr * RS) + c4 * 2;
        uint32_t* dl = (uint32_t*)(Alo + (size_t)rr * RS) + c4 * 2;
        dh[0] = pkh(v.x, v.y);
        dh[1] = pkh(v.z, v.w);
        dl[0] = pkh(v.x - f01.x, v.y - f01.y);
        dl[1] = pkh(v.z - f23.x, v.w - f23.y);
    }
}

// ---------------------------------------------------------------------------
// setup kernels
// ---------------------------------------------------------------------------
__global__ void detect_idx_kernel(const void* __restrict__ idx) {
    if (threadIdx.x == 0 && blockIdx.x == 0) {
        const long long* p = (const long long*)idx;
        int ok = 1;
        for (int i = 0; i < 1024; ++i) {
            long long v = p[i];
            if (v < 0 || v >= (long long)NN) { ok = 0; break; }
        }
        g_idx64 = ok;
    }
}

__global__ void weights_kernel(const float* __restrict__ W1, const float* __restrict__ W2) {
    int m = blockIdx.x;   // 0:W1a 1:W1b 2:W1c 3:W2
    const float* src = (m < 3) ? (W1 + (size_t)m * Dd * Dd) : W2;
    for (int idx = threadIdx.x; idx < 8 * 8 * 32; idx += blockDim.x) {
        int ks = idx >> 8;
        int np = (idx >> 5) & 7;
        int lane = idx & 31;
        int g = lane >> 2, t = lane & 3;
        uint32_t vals[4];
        #pragma unroll
        for (int half = 0; half < 2; ++half) {
            int n = (np * 2 + half) * 8 + g;
            float w0 = src[(size_t)(ks * 16 + 2 * t) * Dd + n];
            float w1 = src[(size_t)(ks * 16 + 2 * t + 1) * Dd + n];
            float w2 = src[(size_t)(ks * 16 + 2 * t + 8) * Dd + n];
            float w3 = src[(size_t)(ks * 16 + 2 * t + 9) * Dd + n];
            vals[half * 2 + 0] = pkh(w0, w1);
            vals[half * 2 + 1] = pkh(w2, w3);
        }
        g_Wfrag[m][ks][np][lane] = make_uint4(vals[0], vals[1], vals[2], vals[3]);
    }
}

// ---------------------------------------------------------------------------
// node projection: P = X @ W1a, Q = X @ W1b (128-node tiles)
// ---------------------------------------------------------------------------
__global__ __launch_bounds__(NT, 2) void node_kernel(const float* __restrict__ node_attr) {
    extern __shared__ char smem[];
    __half* Ahi = (__half*)smem;
    __half* Alo = Ahi + 128 * RS;

    const int tid = threadIdx.x;
    const int lane = tid & 31, w = tid >> 5;
    const int g = lane >> 2, t = lane & 3;
    const int m0 = (w & 3) * 32, nw = w >> 2, nc0 = nw * 64;
    const int r0 = blockIdx.x * 128;

    cvt_tile(Ahi, Alo, node_attr, r0, NN, tid);
    __syncthreads();

    const int lrow = m0 + (lane & 15);
    const uint32_t aOff = (uint32_t)lrow * RS * 2 + (uint32_t)(lane >> 4) * 16;
    const uint32_t aHiA = smem_u32(Ahi) + aOff;
    const uint32_t aLoA = smem_u32(Alo) + aOff;

    float acc[2][8][4];
    #pragma unroll 1
    for (int mat = 0; mat < 2; ++mat) {
        #pragma unroll
        for (int mt = 0; mt < 2; ++mt)
            #pragma unroll
            for (int nt = 0; nt < 8; ++nt)
                #pragma unroll
                for (int j = 0; j < 4; ++j) acc[mt][nt][j] = 0.f;

        gemm2p(acc, aHiA, aLoA, mat, nw, lane);

        float* dst = mat ? g_Q : g_P;
        #pragma unroll
        for (int mt = 0; mt < 2; ++mt) {
            #pragma unroll
            for (int h = 0; h < 2; ++h) {
                int gr = r0 + m0 + mt * 16 + h * 8 + g;
                if (gr < NN) {
                    #pragma unroll
                    for (int nt = 0; nt < 8; ++nt) {
                        int c = nc0 + nt * 8 + 2 * t;
                        *(float2*)(dst + (size_t)gr * Dd + c) =
                            make_float2(acc[mt][nt][h * 2], acc[mt][nt][h * 2 + 1]);
                    }
                }
            }
        }
    }
}

// ---------------------------------------------------------------------------
// fused edge kernel
// ---------------------------------------------------------------------------
__global__ __launch_bounds__(NT, 2) void edge_kernel(
    const float* __restrict__ edge_attr,
    const void* __restrict__ idx,
    const float* __restrict__ b1,
    const float* __restrict__ b2,
    const float* __restrict__ gamma,
    const float* __restrict__ beta,
    float* __restrict__ out) {
    extern __shared__ char smem[];
    __half* Ahi = (__half*)smem;
    __half* Alo = Ahi + 128 * RS;
    float* redS  = (float*)(smem + (size_t)128 * RS * 4);   // [128][2]
    float* redS2 = redS + 256;

    const int tid = threadIdx.x;
    const int lane = tid & 31, w = tid >> 5;
    const int g = lane >> 2, t = lane & 3;
    const int m0 = (w & 3) * 32, nw = w >> 2, nc0 = nw * 64;
    const int e0 = blockIdx.x * 128;
    const int is64 = g_idx64;

    // ---- gather fold: acc = P[s] + Q[r] + b1 BEFORE GEMM1 (overlaps with cvt) ----
    float acc[2][8][4];
    #pragma unroll
    for (int mt = 0; mt < 2; ++mt)
        #pragma unroll
        for (int nt = 0; nt < 8; ++nt)
            #pragma unroll
            for (int j = 0; j < 4; ++j) acc[mt][nt][j] = 0.f;

    #pragma unroll
    for (int mt = 0; mt < 2; ++mt) {
        #pragma unroll
        for (int h = 0; h < 2; ++h) {
            int e = e0 + m0 + mt * 16 + h * 8 + g;
            if (e < NE) {
                int s, rv;
                if (is64) {
                    const long long* pI = (const long long*)idx;
                    s = (int)pI[e]; rv = (int)pI[NE + e];
                } else {
                    const int* pI = (const int*)idx;
                    s = pI[e]; rv = pI[NE + e];
                }
                const float* Pp = g_P + (size_t)s * Dd;
                const float* Qp = g_Q + (size_t)rv * Dd;
                #pragma unroll
                for (int nt = 0; nt < 8; ++nt) {
                    int c = nc0 + nt * 8 + 2 * t;
                    float2 pv = *(const float2*)(Pp + c);
                    float2 qv = *(const float2*)(Qp + c);
                    float2 bv = *(const float2*)(b1 + c);
                    acc[mt][nt][h * 2 + 0] += pv.x + qv.x + bv.x;
                    acc[mt][nt][h * 2 + 1] += pv.y + qv.y + bv.y;
                }
            }
        }
    }

    cvt_tile(Ahi, Alo, edge_attr, e0, NE, tid);
    __syncthreads();

    const int lrow = m0 + (lane & 15);
    const uint32_t aOff = (uint32_t)lrow * RS * 2 + (uint32_t)(lane >> 4) * 16;
    const uint32_t aHiA = smem_u32(Ahi) + aOff;
    const uint32_t aLoA = smem_u32(Alo) + aOff;

    // GEMM1: acc += edge_attr @ W1c ; then ReLU
    gemm2p(acc, aHiA, aLoA, 2, nw, lane);
    #pragma unroll
    for (int mt = 0; mt < 2; ++mt)
        #pragma unroll
        for (int nt = 0; nt < 8; ++nt)
            #pragma unroll
            for (int j = 0; j < 4; ++j) acc[mt][nt][j] = fmaxf(acc[mt][nt][j], 0.f);

    __syncthreads();   // all warps done reading edge A planes

    // store H as fp16 hi/lo back into the A planes
    #pragma unroll
    for (int mt = 0; mt < 2; ++mt) {
        #pragma unroll
        for (int h = 0; h < 2; ++h) {
            int row = m0 + mt * 16 + h * 8 + g;
            #pragma unroll
            for (int nt = 0; nt < 8; ++nt) {
                int c = nc0 + nt * 8 + 2 * t;
                float x0 = acc[mt][nt][h * 2], x1 = acc[mt][nt][h * 2 + 1];
                __half2 hh = __floats2half2_rn(x0, x1);
                float2 hf = __half22float2(hh);
                *(uint32_t*)(Ahi + (size_t)row * RS + c) = pkh(x0, x1);
                *(uint32_t*)(Alo + (size_t)row * RS + c) = pkh(x0 - hf.x, x1 - hf.y);
            }
        }
    }
    __syncthreads();

    #pragma unroll
    for (int mt = 0; mt < 2; ++mt)
        #pragma unroll
        for (int nt = 0; nt < 8; ++nt)
            #pragma unroll
            for (int j = 0; j < 4; ++j) acc[mt][nt][j] = 0.f;

    // GEMM2: H @ W2
    gemm2p(acc, aHiA, aLoA, 3, nw, lane);

    // LayerNorm: add b2, row partial sums, cross-n-warp reduction via smem
    #pragma unroll
    for (int mt = 0; mt < 2; ++mt) {
        #pragma unroll
        for (int h = 0; h < 2; ++h) {
            int row = m0 + mt * 16 + h * 8 + g;
            float s = 0.f, s2 = 0.f;
            #pragma unroll
            for (int nt = 0; nt < 8; ++nt) {
                int c = nc0 + nt * 8 + 2 * t;
                float2 bv = *(const float2*)(b2 + c);
                float v0 = acc[mt][nt][h * 2] + bv.x;
                float v1 = acc[mt][nt][h * 2 + 1] + bv.y;
                acc[mt][nt][h * 2] = v0;
                acc[mt][nt][h * 2 + 1] = v1;
                s += v0 + v1;
                s2 += v0 * v0 + v1 * v1;
            }
            s  += __shfl_xor_sync(0xFFFFFFFFu, s, 1);
            s  += __shfl_xor_sync(0xFFFFFFFFu, s, 2);
            s2 += __shfl_xor_sync(0xFFFFFFFFu, s2, 1);
            s2 += __shfl_xor_sync(0xFFFFFFFFu, s2, 2);
            if (t == 0) {
                redS[row * 2 + nw] = s;
                redS2[row * 2 + nw] = s2;
            }
        }
    }
    __syncthreads();

    #pragma unroll
    for (int mt = 0; mt < 2; ++mt) {
        #pragma unroll
        for (int h = 0; h < 2; ++h) {
            int row = m0 + mt * 16 + h * 8 + g;
            int e = e0 + row;
            if (e < NE) {
                float S  = redS[row * 2] + redS[row * 2 + 1];
                float S2 = redS2[row * 2] + redS2[row * 2 + 1];
                float mu = S * (1.f / 128.f);
                float var = S2 * (1.f / 128.f) - mu * mu;
                float inv = rsqrtf(var + 1e-5f);
                #pragma unroll
                for (int nt = 0; nt < 8; ++nt) {
                    int c = nc0 + nt * 8 + 2 * t;
                    float2 gv = *(const float2*)(gamma + c);
                    float2 bv = *(const float2*)(beta + c);
                    float2 o;
                    o.x = (acc[mt][nt][h * 2] - mu) * inv * gv.x + bv.x;
                    o.y = (acc[mt][nt][h * 2 + 1] - mu) * inv * gv.y + bv.y;
                    *(float2*)(out + (size_t)e * Dd + c) = o;
                }
            }
        }
    }
}

// ---------------------------------------------------------------------------
extern "C" void kernel_launch(void* const* d_in, const int* in_sizes, int n_in,
                              void* d_out, int out_size) {
    const float* node_attr = (const float*)d_in[0];
    const void*  eidx      = d_in[1];
    const float* edge_attr = (const float*)d_in[2];
    const float* W1        = (const float*)d_in[3];
    const float* b1        = (const float*)d_in[4];
    const float* W2        = (const float*)d_in[5];
    const float* b2        = (const float*)d_in[6];
    const float* gamma     = (const float*)d_in[7];
    const float* beta      = (const float*)d_in[8];
    float* out = (float*)d_out;

    cudaFuncSetAttribute(node_kernel, cudaFuncAttributeMaxDynamicSharedMemorySize, SMEM_BYTES);
    cudaFuncSetAttribute(edge_kernel, cudaFuncAttributeMaxDynamicSharedMemorySize, SMEM_BYTES);

    detect_idx_kernel<<<1, 32>>>(eidx);
    weights_kernel<<<4, 256>>>(W1, W2);

    node_kernel<<<(NN + 127) / 128, NT, SMEM_BYTES>>>(node_attr);
    edge_kernel<<<(NE + 127) / 128, NT, SMEM_BYTES>>>(edge_attr, eidx, b1, b2,
                                                      gamma, beta, out);
}